// round 4
// baseline (speedup 1.0000x reference)
#include <cuda_runtime.h>

#define NE 160000
#define NNODE 10000
#define NHEADS 4

// ---------------- scratch (device globals: no allocation allowed) ----------
__device__ float g_scores[NE * NHEADS];   // post-leakyrelu scores
__device__ float g_v[NE * 24];            // v values per edge (8*3 = 24)
__device__ float g_smax[NNODE * NHEADS];
__device__ float g_denom[NNODE * NHEADS];

__device__ __forceinline__ void atomicMaxF(float* addr, float v) {
    if (v >= 0.f) atomicMax((int*)addr, __float_as_int(v));
    else          atomicMin((unsigned int*)addr, __float_as_uint(v));
}

// ---------------- smem layout (float offsets) ------------------------------
// scratch region [0, 16640): W2 tile (256x64=16384) + b2 tile (256)
//   phase-1 aliases inside scratch:
//     ef   [0,    1056)   32 x 33 (pad)
//     W1   [1056, 3104)   64 x 32
//     b1   [3104, 3168)
//     bas  [3168, 3744)   32 x 18
//     fs   [3744, 5312)   32 x 49 (pad)
// h    [16640, 18816)  32 x 68 (pad, float4-aligned rows)
// tmp  [18816, 21920)  32 x 97 (pad)
// conv [21920, 24256)  32 x 73 (pad)
// src  [24256, 24288)  int
// dst  [24288, 24320)  int
#define SMEM_FLOATS 24320
#define SMEM_BYTES  (SMEM_FLOATS * 4)

__global__ void __launch_bounds__(256) k_main(
    const int*   __restrict__ src,  const int*   __restrict__ dst,
    const float* __restrict__ basis,const float* __restrict__ efeat,
    const float* __restrict__ f,    const float* __restrict__ W1,
    const float* __restrict__ b1,   const float* __restrict__ W2,
    const float* __restrict__ b2)
{
    extern __shared__ float sm[];
    float* sW2  = sm;
    float* sB2  = sm + 16384;
    float* sEF  = sm;            // alias (phase 1)
    float* sW1  = sm + 1056;
    float* sB1  = sm + 3104;
    float* sBAS = sm + 3168;
    float* sFS  = sm + 3744;
    float* sH   = sm + 16640;
    float* sTMP = sm + 18816;
    float* sCONV= sm + 21920;
    int*   sSRC = (int*)(sm + 24256);
    int*   sDST = (int*)(sm + 24288);

    const int t  = threadIdx.x;
    const int e0 = blockIdx.x * 32;

    if (t < 32) { sSRC[t] = src[e0 + t]; sDST[t] = dst[e0 + t]; }
    // edge feats: (E,32) -> contiguous 1024 floats for this block
    for (int i = t; i < 1024; i += 256)
        sEF[(i >> 5) * 33 + (i & 31)] = efeat[e0 * 32 + i];
    for (int i = t; i < 2048; i += 256) sW1[i] = W1[i];
    if (t < 64) sB1[t] = b1[t];
    for (int i = t; i < 576; i += 256) sBAS[i] = basis[e0 * 18 + i];
    __syncthreads();

    // gather f[src[e]] : 32 edges x 48 floats
    for (int i = t; i < 1536; i += 256) {
        int e = i / 48; int q = i - e * 48;
        sFS[e * 49 + q] = f[sSRC[e] * 48 + q];
    }
    __syncthreads();

    // ---- h = relu(ef @ W1^T + b1) : 32 x 64 ----
    {
        int e = t & 31; int j0 = (t >> 5) * 8;
        for (int jj = 0; jj < 8; jj++) {
            int j = j0 + jj;
            float acc = sB1[j];
            #pragma unroll
            for (int k = 0; k < 32; k++)
                acc = fmaf(sEF[e * 33 + k], sW1[j * 32 + k], acc);
            sH[e * 68 + j] = fmaxf(acc, 0.f);
        }
    }

    // ---- tmp[e][ii][d] (32 x 32 x 3), ii = m*2+r, k = r*3+d ----
    for (int i = t; i < 3072; i += 256) {
        int e = i / 96; int p = i - e * 96;
        int ii = p / 3; int d = p - ii * 3;
        int m = ii >> 1; int k = (ii & 1) * 3 + d;
        const float* fr = &sFS[e * 49 + m * 3];
        const float* br = &sBAS[e * 18 + k];
        sTMP[e * 97 + p] = fr[0] * br[0] + fr[1] * br[6] + fr[2] * br[12];
    }
    __syncthreads();

    // ---- preload h[e] into 16 float4 registers ----
    const int e  = t & 31;
    const int cl = t >> 5;   // 0..7 : local output channel in this W2 tile
    float4 hr[16];
    {
        const float4* hp = (const float4*)&sH[e * 68];
        #pragma unroll
        for (int i = 0; i < 16; i++) hr[i] = hp[i];
    }

    // ---- 3 W2 tiles of 256 rows; conv[e][c][d] accumulated and stored ----
    for (int tile = 0; tile < 3; tile++) {
        __syncthreads();   // previous consumers of sW2 done
        {
            const float4* g = (const float4*)(W2 + tile * 16384);
            float4* s = (float4*)sW2;
            for (int i = t; i < 4096; i += 256) s[i] = g[i];
            sB2[t] = b2[tile * 256 + t];
        }
        __syncthreads();

        float cd0 = 0.f, cd1 = 0.f, cd2 = 0.f;
        const int rowbase = cl * 32;
        #pragma unroll 1
        for (int m = 0; m < 32; m++) {
            const float4* wr = (const float4*)&sW2[(rowbase + m) << 6];
            float a0 = 0.f, a1 = 0.f, a2 = 0.f, a3 = 0.f;
            #pragma unroll
            for (int q = 0; q < 16; q++) {
                float4 w = wr[q];
                a0 = fmaf(w.x, hr[q].x, a0);
                a1 = fmaf(w.y, hr[q].y, a1);
                a2 = fmaf(w.z, hr[q].z, a2);
                a3 = fmaf(w.w, hr[q].w, a3);
            }
            float rw = (a0 + a1) + (a2 + a3) + sB2[rowbase + m];
            const float* tp = &sTMP[e * 97 + 3 * m];
            cd0 = fmaf(rw, tp[0], cd0);
            cd1 = fmaf(rw, tp[1], cd1);
            cd2 = fmaf(rw, tp[2], cd2);
        }
        int cbase = tile * 24 + cl * 3;
        sCONV[e * 73 + cbase + 0] = cd0;
        sCONV[e * 73 + cbase + 1] = cd1;
        sCONV[e * 73 + cbase + 2] = cd2;
    }
    __syncthreads();

    // ---- attention scores + segment max; stash v ----
    if (t < 128) {
        int ee = t & 31; int hh = t >> 5;   // head 0..3
        const float* cv = &sCONV[ee * 73];
        float acc = 0.f;
        #pragma unroll
        for (int i = 0; i < 6; i++)
            acc = fmaf(cv[hh * 6 + i], cv[24 + hh * 6 + i], acc);
        float s = acc * 0.20412414523193154f;     // 24^-0.5
        s = (s >= 0.f) ? s : 0.2f * s;            // leaky_relu 0.2
        g_scores[(e0 + ee) * 4 + hh] = s;
        atomicMaxF(&g_smax[sDST[ee] * 4 + hh], s);
    }
    for (int i = t; i < 768; i += 256) {
        int ee = i / 24; int p = i - ee * 24;
        g_v[(e0 + ee) * 24 + p] = sCONV[ee * 73 + 48 + p];
    }
}

__global__ void k_init(float* __restrict__ out) {
    int i = blockIdx.x * 256 + threadIdx.x;
    if (i < NNODE * 24) out[i] = 0.f;
    if (i < NNODE * NHEADS) { g_smax[i] = -3.0e38f; g_denom[i] = 0.f; }
}

__global__ void k_denom(const int* __restrict__ dst) {
    int i = blockIdx.x * 256 + threadIdx.x;
    if (i >= NE * NHEADS) return;
    int e = i >> 2, h = i & 3;
    int dn = dst[e];
    float ex = expf(g_scores[i] - g_smax[dn * 4 + h]);
    atomicAdd(&g_denom[dn * 4 + h], ex);
}

__global__ void k_out(const int* __restrict__ dst, float* __restrict__ out) {
    int i = blockIdx.x * 256 + threadIdx.x;
    if (i >= NE * 24) return;
    int e = i / 24; int p = i - e * 24; int h = p / 6;
    int dn = dst[e];
    int si = dn * 4 + h;
    float w = expf(g_scores[e * 4 + h] - g_smax[si]) / g_denom[si];
    atomicAdd(&out[dn * 24 + p], w * g_v[i]);
}

extern "C" void kernel_launch(void* const* d_in, const int* in_sizes, int n_in,
                              void* d_out, int out_size) {
    const int*   src   = (const int*)  d_in[0];
    const int*   dst   = (const int*)  d_in[1];
    const float* basis = (const float*)d_in[2];
    const float* efeat = (const float*)d_in[3];
    const float* f     = (const float*)d_in[4];
    const float* W1    = (const float*)d_in[5];
    const float* b1    = (const float*)d_in[6];
    const float* W2    = (const float*)d_in[7];
    const float* b2    = (const float*)d_in[8];
    float* out = (float*)d_out;

    cudaFuncSetAttribute(k_main, cudaFuncAttributeMaxDynamicSharedMemorySize, SMEM_BYTES);

    k_init<<<(NNODE * 24 + 255) / 256, 256>>>(out);
    k_main<<<NE / 32, 256, SMEM_BYTES>>>(src, dst, basis, efeat, f, W1, b1, W2, b2);
    k_denom<<<(NE * NHEADS + 255) / 256, 256>>>(dst);
    k_out<<<(NE * 24 + 255) / 256, 256>>>(dst, out);
}

// round 7
// speedup vs baseline: 1.7722x; 1.7722x over previous
#include <cuda_runtime.h>
#include <cuda_bf16.h>

#define NE 160000
#define NNODE 10000
#define EB 128
#define NBLK (NE / EB)        // 1250
#define NTILES 96             // 768 channels / 8
#define KSTEP 12              // K=192 / 16

typedef unsigned int u32;
typedef unsigned short u16;
typedef unsigned long long u64;

// ---------------- global scratch -------------------------------------------
__device__ float g_scores[NE * 4];
__device__ float g_v[NE * 24];
__device__ float g_smax[NNODE * 4];
__device__ float g_denom[NNODE * 4];
__device__ __align__(16) u64 g_W2f[NTILES * KSTEP * 32];   // B in fragment order

// ---------------- helpers --------------------------------------------------
__device__ __forceinline__ void mma16816(float& d0, float& d1, float& d2, float& d3,
    u32 a0, u32 a1, u32 a2, u32 a3, u32 b0, u32 b1) {
    asm volatile("mma.sync.aligned.m16n8k16.row.col.f32.bf16.bf16.f32 "
        "{%0,%1,%2,%3}, {%4,%5,%6,%7}, {%8,%9}, {%0,%1,%2,%3};"
        : "+f"(d0), "+f"(d1), "+f"(d2), "+f"(d3)
        : "r"(a0), "r"(a1), "r"(a2), "r"(a3), "r"(b0), "r"(b1));
}
__device__ __forceinline__ void atomicMaxF(float* addr, float v) {
    if (v >= 0.f) atomicMax((int*)addr, __float_as_int(v));
    else          atomicMin((unsigned int*)addr, __float_as_uint(v));
}
__device__ __forceinline__ u16 bf16b(float x) {
    __nv_bfloat16 b = __float2bfloat16(x);
    return *(u16*)&b;
}
// B element of the split-GEMM: k<128 -> hi(W[k&63]); k>=128 -> lo(W[k-128])
__device__ __forceinline__ u16 bsplit(const float* W2, int n, int k) {
    float w = W2[n * 64 + (k & 63)];
    __nv_bfloat16 hi = __float2bfloat16(w);
    if (k < 128) return *(u16*)&hi;
    return bf16b(w - __bfloat162float(hi));
}

// ---------------- smem layout (float offsets) ------------------------------
// R0 [0,8448): FS(6144,s48)+BAS(2304)  ->  A-stage (128 x 132 bf16 = 33792B)
// TMP [8448,20832): 96 rows (m*3+d) x 129
// R_EW [20832,27168): EF(4224,s33)+W1(2048)+b1(64)  ->  conv (128 x 49)
// b2 [27168,27936)   src [27936,28064)   dst [28064,28192)
#define O_FS   0
#define O_BAS  6144
#define O_TMP  8448
#define O_EF   20832
#define O_W1   25056
#define O_B1V  27104
#define O_CONV 20832
#define O_B2   27168
#define O_SRC  27936
#define O_DST  28064
#define SMEM_FLOATS 28192
#define SMEM_BYTES  (SMEM_FLOATS * 4)

// ---------------- W2 -> bf16-split fragment-order buffer -------------------
__global__ void k_prep(const float* __restrict__ W2) {
    int idx = blockIdx.x * 256 + threadIdx.x;
    if (idx >= NTILES * KSTEP * 32) return;
    int lane = idx & 31;
    int rest = idx >> 5;              // ntile*12 + s
    int s = rest % KSTEP;
    int ntile = rest / KSTEP;
    int g = lane >> 2, tig = lane & 3;
    int n = ntile * 8 + g;
    int k0 = s * 16 + tig * 2;
    u32 w0 = (u32)bsplit(W2, n, k0)     | ((u32)bsplit(W2, n, k0 + 1) << 16);
    u32 w1 = (u32)bsplit(W2, n, k0 + 8) | ((u32)bsplit(W2, n, k0 + 9) << 16);
    g_W2f[idx] = ((u64)w1 << 32) | w0;
}

// ---------------- fused main kernel ----------------------------------------
__global__ void __launch_bounds__(256, 2) k_main(
    const int*   __restrict__ src,  const int*   __restrict__ dst,
    const float* __restrict__ basis,const float* __restrict__ efeat,
    const float* __restrict__ f,    const float* __restrict__ W1,
    const float* __restrict__ b1,   const float* __restrict__ b2)
{
    extern __shared__ float sm[];
    const int t = threadIdx.x;
    const int e0 = blockIdx.x * EB;
    int* sSRC = (int*)(sm + O_SRC);
    int* sDST = (int*)(sm + O_DST);

    // ---- phase 0 ----
    if (t < 128) { sSRC[t] = src[e0 + t]; sDST[t] = dst[e0 + t]; }
    for (int i = t; i < 4096; i += 256) sm[O_EF + (i >> 5) * 33 + (i & 31)] = efeat[e0 * 32 + i];
    for (int i = t; i < 2048; i += 256) sm[O_W1 + i] = W1[i];
    if (t < 64) sm[O_B1V + t] = b1[t];
    for (int i = t; i < 2304; i += 256) sm[O_BAS + i] = basis[e0 * 18 + i];
    for (int i = t; i < 768; i += 256) sm[O_B2 + i] = b2[i];
    __syncthreads();
    for (int i = t; i < 6144; i += 256) {                 // gather f[src]
        int e = i / 48, q = i - e * 48;
        sm[O_FS + e * 48 + q] = f[sSRC[e] * 48 + q];
    }
    __syncthreads();

    // ---- tmp[(m*3+d)*129 + e] = fe[e,mm,:] . basis[e,:,r*3+d],  m = 2mm+r --
    for (int i = t; i < 12288; i += 256) {
        int m = i / 384, rem = i - m * 384;
        int d = rem >> 7, e = rem & 127;
        int mm = m >> 1, r = m & 1;
        const float* fr = &sm[O_FS + e * 48 + mm * 3];
        const float* br = &sm[O_BAS + e * 18 + r * 3 + d];
        sm[O_TMP + (m * 3 + d) * 129 + e] = fr[0] * br[0] + fr[1] * br[6] + fr[2] * br[12];
    }
    __syncthreads();

    // ---- h = relu(ef @ W1^T + b1) -> A-stage (hi | lo), overwrites FS/BAS --
    {
        char* Ab = (char*)sm;
        int e = t & 127, j0 = (t >> 7) * 32;
        const float* efr = &sm[O_EF + e * 33];
        for (int jj = 0; jj < 32; jj++) {
            int j = j0 + jj;
            const float* wr = &sm[O_W1 + j * 32];
            float acc = sm[O_B1V + j];
            #pragma unroll
            for (int k = 0; k < 32; k++) acc = fmaf(efr[k], wr[k], acc);
            acc = fmaxf(acc, 0.f);
            __nv_bfloat16 hi = __float2bfloat16(acc);
            float lo = acc - __bfloat162float(hi);
            *(u16*)(Ab + e * 264 + j * 2)        = *(u16*)&hi;
            *(u16*)(Ab + e * 264 + (64 + j) * 2) = bf16b(lo);
        }
    }
    __syncthreads();

    // ---- preload A fragments: 2 M-tiles x 8 K-steps x 4 regs ----
    const int wid = t >> 5, lane = t & 31, g = lane >> 2, tig = lane & 3;
    const int mbase = (wid & 3) * 32;        // this warp's 32 edges
    const int ntbase = (wid >> 2) * 48;      // this warp's 48 N-tiles
    u32 ar[2][8][4];
    {
        const char* Ab = (const char*)sm;
        #pragma unroll
        for (int mt = 0; mt < 2; mt++)
            #pragma unroll
            for (int s = 0; s < 8; s++) {
                int r0 = mbase + mt * 16 + g;
                int k0 = s * 16 + tig * 2;
                ar[mt][s][0] = *(const u32*)(Ab + r0 * 264 + k0 * 2);
                ar[mt][s][1] = *(const u32*)(Ab + (r0 + 8) * 264 + k0 * 2);
                ar[mt][s][2] = *(const u32*)(Ab + r0 * 264 + k0 * 2 + 16);
                ar[mt][s][3] = *(const u32*)(Ab + (r0 + 8) * 264 + k0 * 2 + 16);
            }
    }
    __syncthreads();   // A-stage consumed; conv region (aliases EF/W1) now writable

    // ---- mainloop: 12 channel-groups x 4 N-tiles, no cross-warp sync ------
    const u64* B64 = g_W2f;
    for (int cg = 0; cg < 12; cg++) {
        const int c = ntbase / 4 + cg;       // global channel 0..23
        float cd[4][3] = {{0.f,0.f,0.f},{0.f,0.f,0.f},{0.f,0.f,0.f},{0.f,0.f,0.f}};
        #pragma unroll 2
        for (int q = 0; q < 4; q++) {
            const int ntile = c * 4 + q;
            const u64* Bt = B64 + (size_t)ntile * (KSTEP * 32) + lane;
            float d0a=0.f,d1a=0.f,d2a=0.f,d3a=0.f;
            float d0b=0.f,d1b=0.f,d2b=0.f,d3b=0.f;
            #pragma unroll
            for (int s = 0; s < KSTEP; s++) {
                u64 bw = Bt[s * 32];
                u32 b0 = (u32)bw, b1 = (u32)(bw >> 32);
                const int as = (s < 8) ? s : s - 8;      // k 128..191 reuse hi(h)
                mma16816(d0a,d1a,d2a,d3a, ar[0][as][0],ar[0][as][1],ar[0][as][2],ar[0][as][3], b0,b1);
                mma16816(d0b,d1b,d2b,d3b, ar[1][as][0],ar[1][as][1],ar[1][as][2],ar[1][as][3], b0,b1);
            }
            const int m0 = q * 8 + tig * 2, m1 = m0 + 1;
            const float bv0 = sm[O_B2 + c * 32 + m0];
            const float bv1 = sm[O_B2 + c * 32 + m1];
            d0a += bv0; d1a += bv1; d2a += bv0; d3a += bv1;
            d0b += bv0; d1b += bv1; d2b += bv0; d3b += bv1;
            #pragma unroll
            for (int d = 0; d < 3; d++) {
                const float* T0 = &sm[O_TMP + (m0 * 3 + d) * 129 + mbase + g];
                const float* T1 = &sm[O_TMP + (m1 * 3 + d) * 129 + mbase + g];
                cd[0][d] += d0a * T0[0]  + d1a * T1[0];
                cd[1][d] += d2a * T0[8]  + d3a * T1[8];
                cd[2][d] += d0b * T0[16] + d1b * T1[16];
                cd[3][d] += d2b * T0[24] + d3b * T1[24];
            }
        }
        // quad reduction (lanes 4g..4g+3 hold partials over disjoint m)
        #pragma unroll
        for (int r = 0; r < 4; r++)
            #pragma unroll
            for (int d = 0; d < 3; d++) {
                float v = cd[r][d];
                v += __shfl_xor_sync(0xffffffffu, v, 1);
                v += __shfl_xor_sync(0xffffffffu, v, 2);
                cd[r][d] = v;
            }
        const int e_loc = mbase + g + tig * 8;           // row this lane writes
        float w0, w1, w2;
        if      (tig == 0) { w0 = cd[0][0]; w1 = cd[0][1]; w2 = cd[0][2]; }
        else if (tig == 1) { w0 = cd[1][0]; w1 = cd[1][1]; w2 = cd[1][2]; }
        else if (tig == 2) { w0 = cd[2][0]; w1 = cd[2][1]; w2 = cd[2][2]; }
        else               { w0 = cd[3][0]; w1 = cd[3][1]; w2 = cd[3][2]; }
        if (c < 16) {                                    // k,q -> smem
            float* cv = &sm[O_CONV + e_loc * 49 + c * 3];
            cv[0] = w0; cv[1] = w1; cv[2] = w2;
        } else {                                         // v -> global
            float* gv = &g_v[(size_t)(e0 + e_loc) * 24 + (c - 16) * 3];
            gv[0] = w0; gv[1] = w1; gv[2] = w2;
        }
    }
    __syncthreads();

    // ---- scores + segment max ----
    for (int idx = t; idx < 512; idx += 256) {
        int e = idx & 127, hh = idx >> 7;
        const float* cv = &sm[O_CONV + e * 49];
        float acc = 0.f;
        #pragma unroll
        for (int i2 = 0; i2 < 6; i2++)
            acc = fmaf(cv[hh * 6 + i2], cv[24 + hh * 6 + i2], acc);
        float s = acc * 0.20412414523193154f;            // 24^-0.5
        s = (s >= 0.f) ? s : 0.2f * s;                   // leaky_relu 0.2
        g_scores[(e0 + e) * 4 + hh] = s;
        atomicMaxF(&g_smax[sDST[e] * 4 + hh], s);
    }
    // second half of heads (idx covers 512 = 128e x 4h in the loop above)
}

// ---------------- epilogue kernels (validated in R4) -----------------------
__global__ void k_init(float* __restrict__ out) {
    int i = blockIdx.x * 256 + threadIdx.x;
    if (i < NNODE * 24) out[i] = 0.f;
    if (i < NNODE * 4) { g_smax[i] = -3.0e38f; g_denom[i] = 0.f; }
}
__global__ void k_denom(const int* __restrict__ dst) {
    int i = blockIdx.x * 256 + threadIdx.x;
    if (i >= NE * 4) return;
    int e = i >> 2, h = i & 3;
    int dn = dst[e];
    float ex = expf(g_scores[i] - g_smax[dn * 4 + h]);
    atomicAdd(&g_denom[dn * 4 + h], ex);
}
__global__ void k_out(const int* __restrict__ dst, float* __restrict__ out) {
    int i = blockIdx.x * 256 + threadIdx.x;
    if (i >= NE * 24) return;
    int e = i / 24, p = i - e * 24, h = p / 6;
    int dn = dst[e];
    int si = dn * 4 + h;
    float w = expf(g_scores[e * 4 + h] - g_smax[si]) / g_denom[si];
    atomicAdd(&out[dn * 24 + p], w * g_v[i]);
}

extern "C" void kernel_launch(void* const* d_in, const int* in_sizes, int n_in,
                              void* d_out, int out_size) {
    const int*   src   = (const int*)  d_in[0];
    const int*   dst   = (const int*)  d_in[1];
    const float* basis = (const float*)d_in[2];
    const float* efeat = (const float*)d_in[3];
    const float* f     = (const float*)d_in[4];
    const float* W1    = (const float*)d_in[5];
    const float* b1    = (const float*)d_in[6];
    const float* W2    = (const float*)d_in[7];
    const float* b2    = (const float*)d_in[8];
    float* out = (float*)d_out;

    cudaFuncSetAttribute(k_main, cudaFuncAttributeMaxDynamicSharedMemorySize, SMEM_BYTES);

    k_prep<<<(NTILES * KSTEP * 32 + 255) / 256, 256>>>(W2);
    k_init<<<(NNODE * 24 + 255) / 256, 256>>>(out);
    k_main<<<NBLK, 256, SMEM_BYTES>>>(src, dst, basis, efeat, f, W1, b1, b2);
    k_denom<<<(NE * 4 + 255) / 256, 256>>>(dst);
    k_out<<<(NE * 24 + 255) / 256, 256>>>(dst, out);
}

// round 11
// speedup vs baseline: 1.9743x; 1.1140x over previous
#include <cuda_runtime.h>
#include <cuda_bf16.h>

#define NE 160000
#define NNODE 10000
#define EB 128
#define NBLK (NE / EB)        // 1250
#define NTILES 96             // 768 channels / 8
#define KSTEP 12              // K=192 / 16

typedef unsigned int u32;
typedef unsigned short u16;
typedef unsigned long long u64;

// ---------------- global scratch -------------------------------------------
__device__ float g_scores[NE * 4];
__device__ float g_v[NE * 24];
__device__ float g_smax[NNODE * 4];
__device__ float g_denom[NNODE * 4];
// B fragments, pair-interleaved: [tile][sp(6)][lane(32)][half(2)] u64
__device__ __align__(16) u64 g_W2f[NTILES * KSTEP * 32];

// ---------------- helpers --------------------------------------------------
__device__ __forceinline__ void mma16816(float& d0, float& d1, float& d2, float& d3,
    u32 a0, u32 a1, u32 a2, u32 a3, u32 b0, u32 b1) {
    asm volatile("mma.sync.aligned.m16n8k16.row.col.f32.bf16.bf16.f32 "
        "{%0,%1,%2,%3}, {%4,%5,%6,%7}, {%8,%9}, {%0,%1,%2,%3};"
        : "+f"(d0), "+f"(d1), "+f"(d2), "+f"(d3)
        : "r"(a0), "r"(a1), "r"(a2), "r"(a3), "r"(b0), "r"(b1));
}
__device__ __forceinline__ void atomicMaxF(float* addr, float v) {
    if (v >= 0.f) atomicMax((int*)addr, __float_as_int(v));
    else          atomicMin((unsigned int*)addr, __float_as_uint(v));
}
__device__ __forceinline__ u16 bf16b(float x) {
    __nv_bfloat16 b = __float2bfloat16(x);
    return *(u16*)&b;
}
// B element of the split-GEMM: k<128 -> hi(W[k&63]); k>=128 -> lo(W[k-128])
__device__ __forceinline__ u16 bsplit(const float* W2, int n, int k) {
    float w = W2[n * 64 + (k & 63)];
    __nv_bfloat16 hi = __float2bfloat16(w);
    if (k < 128) return *(u16*)&hi;
    return bf16b(w - __bfloat162float(hi));
}

// ---------------- smem layout (float offsets) ------------------------------
// R0 [0,8448):  phase0 FS(128x48)+BAS(128x18) -> A-stage (128x264B) -> B chunk (6144)
// TMP [8448,21248): 128 e x (3 d x 32 m, stride 100)
// R1 [21248,27584): phase0 EF(128x33)+W1(2048)+b1(64) -> conv (128x49)
// b2 [27584,28352)  src [28352,28480)  dst [28480,28608)
#define O_FS   0
#define O_BAS  6144
#define O_BCH  0
#define O_TMP  8448
#define O_EF   21248
#define O_W1   25472
#define O_B1V  27520
#define O_CONV 21248
#define O_B2   27584
#define O_SRC  28352
#define O_DST  28480
#define SMEM_FLOATS 28608
#define SMEM_BYTES  (SMEM_FLOATS * 4)

// ---------------- W2 -> bf16-split fragment buffer (pair-interleaved) ------
__global__ void k_prep(const float* __restrict__ W2) {
    int idx = blockIdx.x * 256 + threadIdx.x;          // tile*384 + sp*64 + lane*2 + half
    if (idx >= NTILES * KSTEP * 32) return;
    int half = idx & 1;
    int lane = (idx >> 1) & 31;
    int sp   = (idx >> 6) % 6;
    int tile = idx / 384;
    int s = sp * 2 + half;
    int g = lane >> 2, tig = lane & 3;
    int n = tile * 8 + g;
    int k0 = s * 16 + tig * 2;
    u32 w0 = (u32)bsplit(W2, n, k0)     | ((u32)bsplit(W2, n, k0 + 1) << 16);
    u32 w1 = (u32)bsplit(W2, n, k0 + 8) | ((u32)bsplit(W2, n, k0 + 9) << 16);
    g_W2f[idx] = ((u64)w1 << 32) | w0;
}

// ---------------- fused main kernel ----------------------------------------
__global__ void __launch_bounds__(256, 2) k_main(
    const int*   __restrict__ src,  const int*   __restrict__ dst,
    const float* __restrict__ basis,const float* __restrict__ efeat,
    const float* __restrict__ f,    const float* __restrict__ W1,
    const float* __restrict__ b1,   const float* __restrict__ b2)
{
    extern __shared__ float sm[];
    const int t = threadIdx.x;
    const int e0 = blockIdx.x * EB;
    int* sSRC = (int*)(sm + O_SRC);
    int* sDST = (int*)(sm + O_DST);

    // ---- phase 0 ----
    if (t < 128) { sSRC[t] = src[e0 + t]; sDST[t] = dst[e0 + t]; }
    for (int i = t; i < 4096; i += 256) sm[O_EF + (i >> 5) * 33 + (i & 31)] = efeat[e0 * 32 + i];
    for (int i = t; i < 2048; i += 256) sm[O_W1 + i] = W1[i];
    if (t < 64) sm[O_B1V + t] = b1[t];
    for (int i = t; i < 2304; i += 256) sm[O_BAS + i] = basis[e0 * 18 + i];
    for (int i = t; i < 768; i += 256) sm[O_B2 + i] = b2[i];
    __syncthreads();
    for (int i = t; i < 6144; i += 256) {              // gather f[src]
        int e = i / 48, q = i - e * 48;
        sm[O_FS + e * 48 + q] = f[sSRC[e] * 48 + q];
    }
    __syncthreads();

    // ---- tmp[e][d][m] = fe[e,mm,:] . basis[e,:,r*3+d],  m = 2mm+r ----
    for (int i = t; i < 12288; i += 256) {
        int e = i / 96, rem = i - e * 96;
        int d = rem >> 5, m = rem & 31;
        int mm = m >> 1, r = m & 1;
        const float* fr = &sm[O_FS + e * 48 + mm * 3];
        const float* br = &sm[O_BAS + e * 18 + r * 3 + d];
        sm[O_TMP + e * 100 + d * 32 + m] = fr[0] * br[0] + fr[1] * br[6] + fr[2] * br[12];
    }
    __syncthreads();

    // ---- h = relu(ef @ W1^T + b1) -> A-stage (hi | lo), overwrites FS/BAS --
    {
        char* Ab = (char*)sm;
        int e = t & 127, j0 = (t >> 7) * 32;
        const float* efr = &sm[O_EF + e * 33];
        for (int jj = 0; jj < 32; jj++) {
            int j = j0 + jj;
            const float* wr = &sm[O_W1 + j * 32];
            float acc = sm[O_B1V + j];
            #pragma unroll
            for (int k = 0; k < 32; k++) acc = fmaf(efr[k], wr[k], acc);
            acc = fmaxf(acc, 0.f);
            __nv_bfloat16 hi = __float2bfloat16(acc);
            float lo = acc - __bfloat162float(hi);
            *(u16*)(Ab + e * 264 + j * 2)        = *(u16*)&hi;
            *(u16*)(Ab + e * 264 + (64 + j) * 2) = bf16b(lo);
        }
    }
    __syncthreads();

    // ---- preload A fragments: 2 M-tiles x 8 K-steps x 4 regs ----
    const int wid = t >> 5, lane = t & 31, g = lane >> 2, tig = lane & 3;
    const int mbase = (wid & 3) * 32;        // this warp's 32 edges
    const int grp = wid >> 2;                // 0: channels 0..11, 1: 12..23
    u32 ar[2][8][4];
    {
        const char* Ab = (const char*)sm;
        #pragma unroll
        for (int mt = 0; mt < 2; mt++)
            #pragma unroll
            for (int s = 0; s < 8; s++) {
                int r0 = mbase + mt * 16 + g;
                int k0 = s * 16 + tig * 2;
                ar[mt][s][0] = *(const u32*)(Ab + r0 * 264 + k0 * 2);
                ar[mt][s][1] = *(const u32*)(Ab + (r0 + 8) * 264 + k0 * 2);
                ar[mt][s][2] = *(const u32*)(Ab + r0 * 264 + k0 * 2 + 16);
                ar[mt][s][3] = *(const u32*)(Ab + (r0 + 8) * 264 + k0 * 2 + 16);
            }
    }

    // ---- mainloop: 12 cg-steps, B staged via smem --------------------------
    const u64* smB64 = (const u64*)sm;                 // O_BCH = 0
    const float4* gB4 = (const float4*)g_W2f;
    float4* sB4 = (float4*)sm;
    for (int cg = 0; cg < 12; cg++) {
        __syncthreads();                               // prior consumers done (also guards A-stage on cg=0)
        {   // stage 8 ntiles: group0 tiles 4cg.., group1 tiles 48+4cg..  (192 float4/tile)
            const int srcA = (cg * 4) * 192, srcB = (48 + cg * 4) * 192;
            for (int i = t; i < 1536; i += 256) {
                int j = (i < 768) ? (srcA + i) : (srcB + (i - 768));
                sB4[i] = gB4[j];
            }
        }
        __syncthreads();
        const int c = grp * 12 + cg;                   // global channel 0..23
        float cd[4][3] = {{0.f,0.f,0.f},{0.f,0.f,0.f},{0.f,0.f,0.f},{0.f,0.f,0.f}};
        #pragma unroll 1
        for (int q = 0; q < 4; q++) {
            const u64* Bt = smB64 + (grp * 4 + q) * 384 + (lane << 1);
            float d0a=0.f,d1a=0.f,d2a=0.f,d3a=0.f;
            float d0b=0.f,d1b=0.f,d2b=0.f,d3b=0.f;
            #pragma unroll
            for (int sp = 0; sp < 6; sp++) {
                ulonglong2 bw = *(const ulonglong2*)(Bt + sp * 64);
                const int as0 = (sp * 2) & 7, as1 = (sp * 2 + 1) & 7;
                u32 b0 = (u32)bw.x, b1 = (u32)(bw.x >> 32);
                mma16816(d0a,d1a,d2a,d3a, ar[0][as0][0],ar[0][as0][1],ar[0][as0][2],ar[0][as0][3], b0,b1);
                mma16816(d0b,d1b,d2b,d3b, ar[1][as0][0],ar[1][as0][1],ar[1][as0][2],ar[1][as0][3], b0,b1);
                b0 = (u32)bw.y; b1 = (u32)(bw.y >> 32);
                mma16816(d0a,d1a,d2a,d3a, ar[0][as1][0],ar[0][as1][1],ar[0][as1][2],ar[0][as1][3], b0,b1);
                mma16816(d0b,d1b,d2b,d3b, ar[1][as1][0],ar[1][as1][1],ar[1][as1][2],ar[1][as1][3], b0,b1);
            }
            const int m0 = q * 8 + tig * 2;
            const float bv0 = sm[O_B2 + c * 32 + m0];
            const float bv1 = sm[O_B2 + c * 32 + m0 + 1];
            d0a += bv0; d1a += bv1; d2a += bv0; d3a += bv1;
            d0b += bv0; d1b += bv1; d2b += bv0; d3b += bv1;
            #pragma unroll
            for (int d = 0; d < 3; d++) {
                const int base = O_TMP + d * 32 + m0 + (mbase + g) * 100;
                float2 t0 = *(const float2*)&sm[base];
                float2 t1 = *(const float2*)&sm[base + 800];
                float2 t2 = *(const float2*)&sm[base + 1600];
                float2 t3 = *(const float2*)&sm[base + 2400];
                cd[0][d] += d0a * t0.x + d1a * t0.y;
                cd[1][d] += d2a * t1.x + d3a * t1.y;
                cd[2][d] += d0b * t2.x + d1b * t2.y;
                cd[3][d] += d2b * t3.x + d3b * t3.y;
            }
        }
        // quad reduction over tig (partials over disjoint m)
        #pragma unroll
        for (int r = 0; r < 4; r++)
            #pragma unroll
            for (int d = 0; d < 3; d++) {
                float v = cd[r][d];
                v += __shfl_xor_sync(0xffffffffu, v, 1);
                v += __shfl_xor_sync(0xffffffffu, v, 2);
                cd[r][d] = v;
            }
        const int e_loc = mbase + g + tig * 8;
        float w0, w1, w2;
        if      (tig == 0) { w0 = cd[0][0]; w1 = cd[0][1]; w2 = cd[0][2]; }
        else if (tig == 1) { w0 = cd[1][0]; w1 = cd[1][1]; w2 = cd[1][2]; }
        else if (tig == 2) { w0 = cd[2][0]; w1 = cd[2][1]; w2 = cd[2][2]; }
        else               { w0 = cd[3][0]; w1 = cd[3][1]; w2 = cd[3][2]; }
        if (c < 16) {                                  // k,q -> smem conv
            float* cv = &sm[O_CONV + e_loc * 49 + c * 3];
            cv[0] = w0; cv[1] = w1; cv[2] = w2;
        } else {                                       // v -> global
            float* gv = &g_v[(size_t)(e0 + e_loc) * 24 + (c - 16) * 3];
            gv[0] = w0; gv[1] = w1; gv[2] = w2;
        }
    }
    __syncthreads();

    // ---- scores + segment max ----
    for (int idx = t; idx < 512; idx += 256) {
        int e = idx & 127, hh = idx >> 7;
        const float* cv = &sm[O_CONV + e * 49];
        float acc = 0.f;
        #pragma unroll
        for (int i2 = 0; i2 < 6; i2++)
            acc = fmaf(cv[hh * 6 + i2], cv[24 + hh * 6 + i2], acc);
        float s = acc * 0.20412414523193154f;          // 24^-0.5
        s = (s >= 0.f) ? s : 0.2f * s;                 // leaky_relu 0.2
        g_scores[(e0 + e) * 4 + hh] = s;
        atomicMaxF(&g_smax[sDST[e] * 4 + hh], s);
    }
}

// ---------------- epilogue kernels (validated) -----------------------------
__global__ void k_init(float* __restrict__ out) {
    int i = blockIdx.x * 256 + threadIdx.x;
    if (i < NNODE * 24) out[i] = 0.f;
    if (i < NNODE * 4) { g_smax[i] = -3.0e38f; g_denom[i] = 0.f; }
}
__global__ void k_denom(const int* __restrict__ dst) {
    int i = blockIdx.x * 256 + threadIdx.x;
    if (i >= NE * 4) return;
    int e = i >> 2, h = i & 3;
    int dn = dst[e];
    float ex = expf(g_scores[i] - g_smax[dn * 4 + h]);
    atomicAdd(&g_denom[dn * 4 + h], ex);
}
__global__ void k_out(const int* __restrict__ dst, float* __restrict__ out) {
    int i = blockIdx.x * 256 + threadIdx.x;
    if (i >= NE * 24) return;
    int e = i / 24, p = i - e * 24, h = p / 6;
    int dn = dst[e];
    int si = dn * 4 + h;
    float w = expf(g_scores[e * 4 + h] - g_smax[si]) / g_denom[si];
    atomicAdd(&out[dn * 24 + p], w * g_v[i]);
}

extern "C" void kernel_launch(void* const* d_in, const int* in_sizes, int n_in,
                              void* d_out, int out_size) {
    const int*   src   = (const int*)  d_in[0];
    const int*   dst   = (const int*)  d_in[1];
    const float* basis = (const float*)d_in[2];
    const float* efeat = (const float*)d_in[3];
    const float* f     = (const float*)d_in[4];
    const float* W1    = (const float*)d_in[5];
    const float* b1    = (const float*)d_in[6];
    const float* W2    = (const float*)d_in[7];
    const float* b2    = (const float*)d_in[8];
    float* out = (float*)d_out;

    cudaFuncSetAttribute(k_main, cudaFuncAttributeMaxDynamicSharedMemorySize, SMEM_BYTES);

    k_prep<<<(NTILES * KSTEP * 32 + 255) / 256, 256>>>(W2);
    k_init<<<(NNODE * 24 + 255) / 256, 256>>>(out);
    k_main<<<NBLK, 256, SMEM_BYTES>>>(src, dst, basis, efeat, f, W1, b1, b2);
    k_denom<<<(NE * 4 + 255) / 256, 256>>>(dst);
    k_out<<<(NE * 24 + 255) / 256, 256>>>(dst, out);
}

// round 16
// speedup vs baseline: 2.0681x; 1.0475x over previous
#include <cuda_runtime.h>
#include <cuda_bf16.h>

#define NE 160000
#define NNODE 10000
#define EB 128
#define NBLK (NE / EB)        // 1250
#define NTILES 96             // 768 channels / 8
#define KSTEP 12              // K=192 / 16

typedef unsigned int u32;
typedef unsigned short u16;
typedef unsigned long long u64;

// ---------------- global scratch -------------------------------------------
__device__ float g_scores[NE * 4];
__device__ __align__(16) float g_v[NE * 24];
__device__ float g_smax[NNODE * 4];
__device__ float g_denom[NNODE * 4];
// B fragments, pair-interleaved: [tile][sp(6)][lane(32)][half(2)] u64
__device__ __align__(16) u64 g_W2f[NTILES * KSTEP * 32];

// ---------------- helpers --------------------------------------------------
__device__ __forceinline__ void mma16816(float& d0, float& d1, float& d2, float& d3,
    u32 a0, u32 a1, u32 a2, u32 a3, u32 b0, u32 b1) {
    asm volatile("mma.sync.aligned.m16n8k16.row.col.f32.bf16.bf16.f32 "
        "{%0,%1,%2,%3}, {%4,%5,%6,%7}, {%8,%9}, {%0,%1,%2,%3};"
        : "+f"(d0), "+f"(d1), "+f"(d2), "+f"(d3)
        : "r"(a0), "r"(a1), "r"(a2), "r"(a3), "r"(b0), "r"(b1));
}
__device__ __forceinline__ void atomicMaxF(float* addr, float v) {
    if (v >= 0.f) atomicMax((int*)addr, __float_as_int(v));
    else          atomicMin((unsigned int*)addr, __float_as_uint(v));
}
__device__ __forceinline__ u16 bf16b(float x) {
    __nv_bfloat16 b = __float2bfloat16(x);
    return *(u16*)&b;
}
// B element of the split-GEMM: k<128 -> hi(W[k&63]); k>=128 -> lo(W[k-128])
__device__ __forceinline__ u16 bsplit(const float* W2, int n, int k) {
    float w = W2[n * 64 + (k & 63)];
    __nv_bfloat16 hi = __float2bfloat16(w);
    if (k < 128) return *(u16*)&hi;
    return bf16b(w - __bfloat162float(hi));
}

// ---------------- smem layout (float offsets) ------------------------------
// R0 [0,8448):  phase0 FS(128x48)+BAS(128x18) -> A-stage (128x264B) -> B chunk (6144)
// TMP [8448,21248): 128 e x (3 d x 32 m, stride 100)
// R1 [21248,27584): phase0 EF(128x33)+W1(2048)+b1(64) -> conv (128x49)
// b2 [27584,28352)  src [28352,28480)  dst [28480,28608)
#define O_FS   0
#define O_BAS  6144
#define O_BCH  0
#define O_TMP  8448
#define O_EF   21248
#define O_W1   25472
#define O_B1V  27520
#define O_CONV 21248
#define O_B2   27584
#define O_SRC  28352
#define O_DST  28480
#define SMEM_FLOATS 28608
#define SMEM_BYTES  (SMEM_FLOATS * 4)

// ---------------- W2 -> split fragments  +  init (merged) ------------------
__global__ void k_prep(const float* __restrict__ W2, float* __restrict__ out) {
    int idx = blockIdx.x * 256 + threadIdx.x;
    if (idx < NNODE * 24) out[idx] = 0.f;
    if (idx < NNODE * 4) { g_smax[idx] = -3.0e38f; g_denom[idx] = 0.f; }
    if (idx >= NTILES * KSTEP * 32) return;
    int half = idx & 1;
    int lane = (idx >> 1) & 31;
    int sp   = (idx >> 6) % 6;
    int tile = idx / 384;
    int s = sp * 2 + half;
    int g = lane >> 2, tig = lane & 3;
    int n = tile * 8 + g;
    int k0 = s * 16 + tig * 2;
    u32 w0 = (u32)bsplit(W2, n, k0)     | ((u32)bsplit(W2, n, k0 + 1) << 16);
    u32 w1 = (u32)bsplit(W2, n, k0 + 8) | ((u32)bsplit(W2, n, k0 + 9) << 16);
    g_W2f[idx] = ((u64)w1 << 32) | w0;
}

// ---------------- fused main kernel ----------------------------------------
__global__ void __launch_bounds__(256, 2) k_main(
    const int*   __restrict__ src,  const int*   __restrict__ dst,
    const float* __restrict__ basis,const float* __restrict__ efeat,
    const float* __restrict__ f,    const float* __restrict__ W1,
    const float* __restrict__ b1,   const float* __restrict__ b2)
{
    extern __shared__ float sm[];
    const int t = threadIdx.x;
    const int e0 = blockIdx.x * EB;
    int* sSRC = (int*)(sm + O_SRC);
    int* sDST = (int*)(sm + O_DST);

    // ---- phase 0 ----
    if (t < 128) { sSRC[t] = src[e0 + t]; sDST[t] = dst[e0 + t]; }
    for (int i = t; i < 4096; i += 256) sm[O_EF + (i >> 5) * 33 + (i & 31)] = efeat[e0 * 32 + i];
    for (int i = t; i < 2048; i += 256) sm[O_W1 + i] = W1[i];
    if (t < 64) sm[O_B1V + t] = b1[t];
    for (int i = t; i < 2304; i += 256) sm[O_BAS + i] = basis[e0 * 18 + i];
    for (int i = t; i < 768; i += 256) sm[O_B2 + i] = b2[i];
    __syncthreads();
    for (int i = t; i < 6144; i += 256) {              // gather f[src]
        int e = i / 48, q = i - e * 48;
        sm[O_FS + e * 48 + q] = f[sSRC[e] * 48 + q];
    }
    __syncthreads();

    // ---- tmp[e][d][m] = fe[e,mm,:] . basis[e,:,r*3+d],  m = 2mm+r ----
    for (int i = t; i < 12288; i += 256) {
        int e = i / 96, rem = i - e * 96;
        int d = rem >> 5, m = rem & 31;
        int mm = m >> 1, r = m & 1;
        const float* fr = &sm[O_FS + e * 48 + mm * 3];
        const float* br = &sm[O_BAS + e * 18 + r * 3 + d];
        sm[O_TMP + e * 100 + d * 32 + m] = fr[0] * br[0] + fr[1] * br[6] + fr[2] * br[12];
    }
    __syncthreads();

    // ---- h = relu(ef @ W1^T + b1) -> A-stage (hi | lo), overwrites FS/BAS --
    {
        char* Ab = (char*)sm;
        int e = t & 127, j0 = (t >> 7) * 32;
        float efr[32];
        #pragma unroll
        for (int k = 0; k < 32; k++) efr[k] = sm[O_EF + e * 33 + k];
        for (int jj = 0; jj < 32; jj++) {
            int j = j0 + jj;
            const float4* wr4 = (const float4*)&sm[O_W1 + j * 32];   // broadcast
            float acc = sm[O_B1V + j];
            #pragma unroll
            for (int k4 = 0; k4 < 8; k4++) {
                float4 w = wr4[k4];
                acc = fmaf(efr[k4 * 4 + 0], w.x, acc);
                acc = fmaf(efr[k4 * 4 + 1], w.y, acc);
                acc = fmaf(efr[k4 * 4 + 2], w.z, acc);
                acc = fmaf(efr[k4 * 4 + 3], w.w, acc);
            }
            acc = fmaxf(acc, 0.f);
            __nv_bfloat16 hi = __float2bfloat16(acc);
            float lo = acc - __bfloat162float(hi);
            *(u16*)(Ab + e * 264 + j * 2)        = *(u16*)&hi;
            *(u16*)(Ab + e * 264 + (64 + j) * 2) = bf16b(lo);
        }
    }
    __syncthreads();

    // ---- preload A fragments: 2 M-tiles x 8 K-steps x 4 regs ----
    const int wid = t >> 5, lane = t & 31, g = lane >> 2, tig = lane & 3;
    const int mbase = (wid & 3) * 32;        // this warp's 32 edges
    const int grp = wid >> 2;                // 0: channels 0..11, 1: 12..23
    u32 ar[2][8][4];
    {
        const char* Ab = (const char*)sm;
        #pragma unroll
        for (int mt = 0; mt < 2; mt++)
            #pragma unroll
            for (int s = 0; s < 8; s++) {
                int r0 = mbase + mt * 16 + g;
                int k0 = s * 16 + tig * 2;
                ar[mt][s][0] = *(const u32*)(Ab + r0 * 264 + k0 * 2);
                ar[mt][s][1] = *(const u32*)(Ab + (r0 + 8) * 264 + k0 * 2);
                ar[mt][s][2] = *(const u32*)(Ab + r0 * 264 + k0 * 2 + 16);
                ar[mt][s][3] = *(const u32*)(Ab + (r0 + 8) * 264 + k0 * 2 + 16);
            }
    }

    // ---- mainloop: 12 cg-steps, B staged via smem --------------------------
    const u64* smB64 = (const u64*)sm;                 // O_BCH = 0
    const float4* gB4 = (const float4*)g_W2f;
    float4* sB4 = (float4*)sm;
    for (int cg = 0; cg < 12; cg++) {
        __syncthreads();                               // prior consumers done (also guards A-stage on cg=0)
        {   // stage 8 ntiles: group0 tiles 4cg.., group1 tiles 48+4cg..  (192 float4/tile)
            const int srcA = (cg * 4) * 192, srcB = (48 + cg * 4) * 192;
            for (int i = t; i < 1536; i += 256) {
                int j = (i < 768) ? (srcA + i) : (srcB + (i - 768));
                sB4[i] = gB4[j];
            }
        }
        __syncthreads();
        const int c = grp * 12 + cg;                   // global channel 0..23
        float cd[4][3] = {{0.f,0.f,0.f},{0.f,0.f,0.f},{0.f,0.f,0.f},{0.f,0.f,0.f}};
        #pragma unroll 1
        for (int q = 0; q < 4; q++) {
            const u64* Bt = smB64 + (grp * 4 + q) * 384 + (lane << 1);
            float d0a=0.f,d1a=0.f,d2a=0.f,d3a=0.f;
            float d0b=0.f,d1b=0.f,d2b=0.f,d3b=0.f;
            #pragma unroll
            for (int sp = 0; sp < 6; sp++) {
                ulonglong2 bw = *(const ulonglong2*)(Bt + sp * 64);
                const int as0 = (sp * 2) & 7, as1 = (sp * 2 + 1) & 7;
                u32 b0 = (u32)bw.x, b1 = (u32)(bw.x >> 32);
                mma16816(d0a,d1a,d2a,d3a, ar[0][as0][0],ar[0][as0][1],ar[0][as0][2],ar[0][as0][3], b0,b1);
                mma16816(d0b,d1b,d2b,d3b, ar[1][as0][0],ar[1][as0][1],ar[1][as0][2],ar[1][as0][3], b0,b1);
                b0 = (u32)bw.y; b1 = (u32)(bw.y >> 32);
                mma16816(d0a,d1a,d2a,d3a, ar[0][as1][0],ar[0][as1][1],ar[0][as1][2],ar[0][as1][3], b0,b1);
                mma16816(d0b,d1b,d2b,d3b, ar[1][as1][0],ar[1][as1][1],ar[1][as1][2],ar[1][as1][3], b0,b1);
            }
            const int m0 = q * 8 + tig * 2;
            const float bv0 = sm[O_B2 + c * 32 + m0];
            const float bv1 = sm[O_B2 + c * 32 + m0 + 1];
            d0a += bv0; d1a += bv1; d2a += bv0; d3a += bv1;
            d0b += bv0; d1b += bv1; d2b += bv0; d3b += bv1;
            #pragma unroll
            for (int d = 0; d < 3; d++) {
                const int base = O_TMP + d * 32 + m0 + (mbase + g) * 100;
                float2 t0 = *(const float2*)&sm[base];
                float2 t1 = *(const float2*)&sm[base + 800];
                float2 t2 = *(const float2*)&sm[base + 1600];
                float2 t3 = *(const float2*)&sm[base + 2400];
                cd[0][d] += d0a * t0.x + d1a * t0.y;
                cd[1][d] += d2a * t1.x + d3a * t1.y;
                cd[2][d] += d0b * t2.x + d1b * t2.y;
                cd[3][d] += d2b * t3.x + d3b * t3.y;
            }
        }
        // quad reduction over tig (partials over disjoint m)
        #pragma unroll
        for (int r = 0; r < 4; r++)
            #pragma unroll
            for (int d = 0; d < 3; d++) {
                float v = cd[r][d];
                v += __shfl_xor_sync(0xffffffffu, v, 1);
                v += __shfl_xor_sync(0xffffffffu, v, 2);
                cd[r][d] = v;
            }
        const int e_loc = mbase + g + tig * 8;
        float w0, w1, w2;
        if      (tig == 0) { w0 = cd[0][0]; w1 = cd[0][1]; w2 = cd[0][2]; }
        else if (tig == 1) { w0 = cd[1][0]; w1 = cd[1][1]; w2 = cd[1][2]; }
        else if (tig == 2) { w0 = cd[2][0]; w1 = cd[2][1]; w2 = cd[2][2]; }
        else               { w0 = cd[3][0]; w1 = cd[3][1]; w2 = cd[3][2]; }
        if (c < 16) {                                  // k,q -> smem conv
            float* cv = &sm[O_CONV + e_loc * 49 + c * 3];
            cv[0] = w0; cv[1] = w1; cv[2] = w2;
        } else {                                       // v -> global
            float* gv = &g_v[(size_t)(e0 + e_loc) * 24 + (c - 16) * 3];
            gv[0] = w0; gv[1] = w1; gv[2] = w2;
        }
    }
    __syncthreads();

    // ---- scores + segment max ----
    for (int idx = t; idx < 512; idx += 256) {
        int e = idx & 127, hh = idx >> 7;
        const float* cv = &sm[O_CONV + e * 49];
        float acc = 0.f;
        #pragma unroll
        for (int i2 = 0; i2 < 6; i2++)
            acc = fmaf(cv[hh * 6 + i2], cv[24 + hh * 6 + i2], acc);
        float s = acc * 0.20412414523193154f;          // 24^-0.5
        s = (s >= 0.f) ? s : 0.2f * s;                 // leaky_relu 0.2
        g_scores[(e0 + e) * 4 + hh] = s;
        atomicMaxF(&g_smax[sDST[e] * 4 + hh], s);
    }
}

// ---------------- epilogue kernels -----------------------------------------
__global__ void k_denom(const int* __restrict__ dst) {
    int i = blockIdx.x * 256 + threadIdx.x;
    if (i >= NE * 4) return;
    int e = i >> 2, h = i & 3;
    int dn = dst[e];
    float ex = expf(g_scores[i] - g_smax[dn * 4 + h]);
    atomicAdd(&g_denom[dn * 4 + h], ex);
}
__global__ void k_out(const int* __restrict__ dst, float* __restrict__ out) {
    int i = blockIdx.x * 256 + threadIdx.x;
    if (i >= NE * 4) return;
    int e = i >> 2, h = i & 3;
    int dn = dst[e];
    int si = dn * 4 + h;
    float w = expf(g_scores[i] - g_smax[si]) / g_denom[si];
    const float2* v2 = (const float2*)&g_v[(size_t)e * 24 + h * 6];
    float* op = &out[dn * 24 + h * 6];
    #pragma unroll
    for (int j = 0; j < 3; j++) {
        float2 v = v2[j];
        atomicAdd(op + 2 * j,     w * v.x);
        atomicAdd(op + 2 * j + 1, w * v.y);
    }
}

extern "C" void kernel_launch(void* const* d_in, const int* in_sizes, int n_in,
                              void* d_out, int out_size) {
    const int*   src   = (const int*)  d_in[0];
    const int*   dst   = (const int*)  d_in[1];
    const float* basis = (const float*)d_in[2];
    const float* efeat = (const float*)d_in[3];
    const float* f     = (const float*)d_in[4];
    const float* W1    = (const float*)d_in[5];
    const float* b1    = (const float*)d_in[6];
    const float* W2    = (const float*)d_in[7];
    const float* b2    = (const float*)d_in[8];
    float* out = (float*)d_out;

    cudaFuncSetAttribute(k_main, cudaFuncAttributeMaxDynamicSharedMemorySize, SMEM_BYTES);

    k_prep<<<(NNODE * 24 + 255) / 256, 256>>>(W2, out);   // prep + init merged
    k_main<<<NBLK, 256, SMEM_BYTES>>>(src, dst, basis, efeat, f, W1, b1, b2);
    k_denom<<<(NE * 4 + 255) / 256, 256>>>(dst);
    k_out<<<(NE * 4 + 255) / 256, 256>>>(dst, out);
}